// round 3
// baseline (speedup 1.0000x reference)
#include <cuda_runtime.h>

#define MAXN 400000
#define MAXF 2000000
#define MAXE (4 * MAXF)             // max crossing edges (<=4 per valid tet)
#define MAXSLOTNS (6 * MAXF)        // slot namespace (6f+e) for idxmap
#define MAXVAL (MAXN + MAXE)
#define MAXT (3 * MAXF)
#define TPB 256
#define GRID(n) (((n) + TPB - 1) / TPB)
#define FULL 0xffffffffu

// ---------------------------------------------------------------------------
// Tables
// ---------------------------------------------------------------------------
__device__ const int d_tri[16][6] = {
    {-1,-1,-1,-1,-1,-1},{1,0,2,-1,-1,-1},{4,0,3,-1,-1,-1},{1,4,2,1,3,4},
    {3,1,5,-1,-1,-1},{2,3,0,2,5,3},{1,4,0,1,5,4},{4,2,5,-1,-1,-1},
    {4,5,2,-1,-1,-1},{4,1,0,4,5,1},{3,2,0,3,5,2},{1,3,5,-1,-1,-1},
    {4,1,2,4,3,1},{3,0,4,-1,-1,-1},{2,0,1,-1,-1,-1},{-1,-1,-1,-1,-1,-1}};
__device__ const int d_tet[16][12] = {
    {-1,-1,-1,-1,-1,-1,-1,-1,-1,-1,-1,-1},{0,4,5,6,-1,-1,-1,-1,-1,-1,-1,-1},
    {1,4,8,7,-1,-1,-1,-1,-1,-1,-1,-1},{7,1,8,6,5,1,7,6,5,0,1,6},
    {2,5,7,9,-1,-1,-1,-1,-1,-1,-1,-1},{4,0,6,7,9,0,7,6,7,0,9,2},
    {4,1,9,8,5,1,9,4,5,1,2,9},{6,0,1,2,8,6,1,2,9,6,8,2},
    {3,6,9,8,-1,-1,-1,-1,-1,-1,-1,-1},{5,0,4,8,5,0,8,3,5,8,9,3},
    {1,4,7,3,4,7,6,3,9,6,7,3},{0,1,5,3,5,1,9,3,5,1,7,9},
    {5,2,3,7,3,6,5,8,3,5,7,8},{0,4,7,8,0,3,8,7,0,3,7,2},
    {4,1,2,3,4,3,2,5,4,3,5,6},{0,1,2,3,-1,-1,-1,-1,-1,-1,-1,-1}};
__device__ const int d_be[12] = {0,1, 0,2, 0,3, 1,2, 1,3, 2,3};

__device__ __forceinline__ unsigned f_valid(unsigned ti) { return (0x7FFEu >> ti) & 1u; }
__device__ __forceinline__ unsigned f_nt1(unsigned ti)   { return (0x6996u >> ti) & 1u; }
__device__ __forceinline__ unsigned f_ntt1(unsigned ti)  { return (0x0116u >> ti) & 1u; }

__device__ __forceinline__ unsigned long long packflags(unsigned ti) {
    unsigned v  = f_valid(ti);
    unsigned n1 = v & f_nt1(ti);
    unsigned t1 = v & f_ntt1(ti);
    unsigned n2 = v ^ n1;
    unsigned t3 = v ^ t1;
    unsigned in = (ti == 15u) ? 1u : 0u;
    return (unsigned long long)n1
         | ((unsigned long long)n2 << 12)
         | ((unsigned long long)t1 << 24)
         | ((unsigned long long)t3 << 36)
         | ((unsigned long long)in << 48);
}

// ---------------------------------------------------------------------------
// Scratch
// ---------------------------------------------------------------------------
__device__ unsigned           g_obits[(MAXN + 31) / 32];
__device__ unsigned char      g_ti[MAXF];
__device__ unsigned           g_bcnt[MAXN];
__device__ unsigned           g_boff[MAXN];
__device__ unsigned           g_bfill[MAXN];
__device__ unsigned           g_ucnt[MAXN];
__device__ unsigned           g_urank[MAXN];
__device__ unsigned long long g_keys[MAXE];
__device__ int                g_idxmap[MAXSLOTNS];
__device__ int                g_uea[MAXE];
__device__ int                g_ueb[MAXE];
__device__ int4               g_alltets[MAXT];
__device__ uint4              g_pres4[(MAXVAL + 15) / 16];
__device__ unsigned           g_rank2[MAXVAL];
__device__ unsigned           g_partf[5 * 1024];
__device__ unsigned           g_part2[4096];
__device__ unsigned           g_cnt[16];
// g_cnt: [0]=E [1]=NT1 [2]=NT2 [3]=T1 [4]=T3 [5]=INNER [6]=U [8]=T [9]=N+E

// ---------------------------------------------------------------------------
// init: occ bitset via ballot + clear bucket counters
// ---------------------------------------------------------------------------
__global__ void k_init(const float* __restrict__ sdf, const float* __restrict__ th, int N) {
    int gt = blockIdx.x * blockDim.x + threadIdx.x;
    int lane = threadIdx.x & 31;
    int warp = gt >> 5;
    float t = *th;
    int base = warp * 128;
#pragma unroll
    for (int it = 0; it < 4; it++) {
        int v = base + it * 32 + lane;
        unsigned o = 0;
        if (v < N) { float s = sdf[v]; o = (s > 0.0f && s <= t) ? 1u : 0u; }
        unsigned bal = __ballot_sync(FULL, o);
        if (lane == 0 && base + it * 32 < N) g_obits[warp * 4 + it] = bal;
    }
    int i4 = gt * 4;
#pragma unroll
    for (int j = 0; j < 4; j++) {
        int i = i4 + j;
        if (i < N) { g_bcnt[i] = 0u; g_bfill[i] = 0u; }
    }
}

// ---------------------------------------------------------------------------
// classify + crossing-edge bucket histogram
// ---------------------------------------------------------------------------
__global__ void k_ti(const int4* __restrict__ tet, int F) {
    int f = blockIdx.x * blockDim.x + threadIdx.x;
    if (f >= F) return;
    int4 q = tet[f];
    int v[4] = {q.x, q.y, q.z, q.w};
    unsigned ti = ((g_obits[v[0] >> 5] >> (v[0] & 31)) & 1u)
                | (((g_obits[v[1] >> 5] >> (v[1] & 31)) & 1u) << 1)
                | (((g_obits[v[2] >> 5] >> (v[2] & 31)) & 1u) << 2)
                | (((g_obits[v[3] >> 5] >> (v[3] & 31)) & 1u) << 3);
    g_ti[f] = (unsigned char)ti;
    if (f_valid(ti)) {
#pragma unroll
        for (int e = 0; e < 6; e++) {
            int p0 = d_be[2 * e], p1 = d_be[2 * e + 1];
            if (((ti >> p0) ^ (ti >> p1)) & 1u) {
                int a = v[p0], b = v[p1];
                int amin = a < b ? a : b;
                atomicAdd(&g_bcnt[amin], 1u);
            }
        }
    }
}

// ---------------------------------------------------------------------------
// 5-channel flag reduce (block partials) + partial scan
// ---------------------------------------------------------------------------
__global__ void fs_k1(int F) {
    __shared__ unsigned long long sh[TPB];
    int t = threadIdx.x;
    int base = blockIdx.x * (TPB * 8) + t * 8;
    unsigned long long p = 0;
#pragma unroll
    for (int i = 0; i < 8; i++) {
        int f = base + i;
        if (f < F) p += packflags(g_ti[f]);
    }
    sh[t] = p; __syncthreads();
    for (int d = TPB / 2; d > 0; d >>= 1) {
        if (t < d) sh[t] += sh[t + d];
        __syncthreads();
    }
    if (t == 0) {
        unsigned long long s = sh[0];
        g_partf[0 * 1024 + blockIdx.x] = (unsigned)(s & 0xFFF);
        g_partf[1 * 1024 + blockIdx.x] = (unsigned)((s >> 12) & 0xFFF);
        g_partf[2 * 1024 + blockIdx.x] = (unsigned)((s >> 24) & 0xFFF);
        g_partf[3 * 1024 + blockIdx.x] = (unsigned)((s >> 36) & 0xFFF);
        g_partf[4 * 1024 + blockIdx.x] = (unsigned)((s >> 48) & 0xFFF);
    }
}

__global__ void fs_k2(int nb) {
    __shared__ unsigned sh[1024];
    int t = threadIdx.x;
    for (int c = 0; c < 5; c++) {
        unsigned x = (t < nb) ? g_partf[c * 1024 + t] : 0u;
        sh[t] = x; __syncthreads();
        for (int d = 1; d < 1024; d <<= 1) {
            unsigned y = 0;
            if (t >= d) y = sh[t - d];
            __syncthreads();
            if (t >= d) sh[t] += y;
            __syncthreads();
        }
        if (t < nb) g_partf[c * 1024 + t] = sh[t] - x;
        if (t == 0) g_cnt[1 + c] = sh[1023];
        __syncthreads();
    }
}

// ---------------------------------------------------------------------------
// Generic u32 scan (bcnt->boff, ucnt->urank)
// ---------------------------------------------------------------------------
__device__ __forceinline__ unsigned* selarr(int s) {
    switch (s) {
        case 0: return g_bcnt;
        case 1: return g_boff;
        case 2: return g_ucnt;
        default: return g_urank;
    }
}

__global__ void s_k1(int insel, int outsel, int n) {
    __shared__ unsigned sh[TPB];
    const unsigned* in = selarr(insel);
    unsigned* out = selarr(outsel);
    int t = threadIdx.x;
    int base = blockIdx.x * (TPB * 8) + t * 8;
    unsigned v[8]; unsigned s = 0;
#pragma unroll
    for (int i = 0; i < 8; i++) {
        unsigned x = (base + i < n) ? in[base + i] : 0u;
        v[i] = s; s += x;
    }
    sh[t] = s; __syncthreads();
    for (int d = 1; d < TPB; d <<= 1) {
        unsigned y = 0;
        if (t >= d) y = sh[t - d];
        __syncthreads();
        if (t >= d) sh[t] += y;
        __syncthreads();
    }
    unsigned off = (t > 0) ? sh[t - 1] : 0u;
    if (t == 0) g_part2[blockIdx.x] = sh[TPB - 1];
    __syncthreads();
#pragma unroll
    for (int i = 0; i < 8; i++)
        if (base + i < n) out[base + i] = v[i] + off;
}

__global__ void s_k2(int nb, int counterIdx, int N) {
    __shared__ unsigned sh[1024];
    __shared__ unsigned carry_s;
    int t = threadIdx.x;
    if (t == 0) carry_s = 0;
    __syncthreads();
    for (int base = 0; base < nb; base += 1024) {
        int i = base + t;
        unsigned x = (i < nb) ? g_part2[i] : 0u;
        sh[t] = x; __syncthreads();
        for (int d = 1; d < 1024; d <<= 1) {
            unsigned y = 0;
            if (t >= d) y = sh[t - d];
            __syncthreads();
            if (t >= d) sh[t] += y;
            __syncthreads();
        }
        unsigned c = carry_s;
        unsigned excl = c + ((t > 0) ? sh[t - 1] : 0u);
        unsigned tot = sh[1023];
        __syncthreads();
        if (i < nb) g_part2[i] = excl;
        if (t == 0) carry_s = c + tot;
        __syncthreads();
    }
    if (t == 0 && counterIdx >= 0) {
        g_cnt[counterIdx] = carry_s;
        if (counterIdx == 0) {   // E finalized: derive T and N+E
            g_cnt[8] = g_cnt[3] + 3u * g_cnt[4] + g_cnt[5];
            g_cnt[9] = (unsigned)N + carry_s;
        }
    }
}

__global__ void s_k3(int outsel, int n) {
    unsigned* out = selarr(outsel);
    unsigned add = g_part2[blockIdx.x];
    int base = blockIdx.x * (TPB * 8) + threadIdx.x * 8;
#pragma unroll
    for (int i = 0; i < 8; i++)
        if (base + i < n) out[base + i] += add;
}

static void run_scan(int insel, int outsel, int n, int counterIdx, int N) {
    int nb = (n + TPB * 8 - 1) / (TPB * 8);
    s_k1<<<nb, TPB>>>(insel, outsel, n);
    s_k2<<<1, 1024>>>(nb, counterIdx, N);
    s_k3<<<nb, TPB>>>(outsel, n);
}

// ---------------------------------------------------------------------------
// scatter crossing edges into buckets
// ---------------------------------------------------------------------------
__global__ void k_scatter(const int4* __restrict__ tet, int F) {
    int f = blockIdx.x * blockDim.x + threadIdx.x;
    if (f >= F) return;
    unsigned ti = g_ti[f];
    if (!f_valid(ti)) return;
    int4 q = tet[f];
    int v[4] = {q.x, q.y, q.z, q.w};
#pragma unroll
    for (int e = 0; e < 6; e++) {
        int p0 = d_be[2 * e], p1 = d_be[2 * e + 1];
        if (((ti >> p0) ^ (ti >> p1)) & 1u) {
            int a = v[p0], b = v[p1];
            int amin = a < b ? a : b;
            int bmax = a < b ? b : a;
            unsigned p = g_boff[amin] + atomicAdd(&g_bfill[amin], 1u);
            unsigned slot = (unsigned)(6 * f + e);
            g_keys[p] = ((unsigned long long)(unsigned)bmax << 24) | (unsigned long long)slot;
        }
    }
}

// ---------------------------------------------------------------------------
// warp-per-bucket sort (register bitonic, shuffles)
// ---------------------------------------------------------------------------
__device__ __forceinline__ unsigned long long warp_bitonic(unsigned long long v, int lane) {
#pragma unroll
    for (int k2 = 2; k2 <= 32; k2 <<= 1) {
#pragma unroll
        for (int j = k2 >> 1; j > 0; j >>= 1) {
            unsigned long long o = __shfl_xor_sync(FULL, v, j);
            bool up = ((lane & k2) == 0);
            bool low = ((lane & j) == 0);
            bool keepMin = (up == low);
            bool less = v < o;
            v = (keepMin == less) ? v : o;
        }
    }
    return v;
}

__global__ void k_sort1(int N) {
    int gw = (blockIdx.x * blockDim.x + threadIdx.x) >> 5;
    int lane = threadIdx.x & 31;
    if (gw >= N) return;
    unsigned off = g_boff[gw];
    unsigned L = g_bcnt[gw];
    unsigned u = 0;
    if (L <= 32u) {
        unsigned long long v = (lane < (int)L) ? g_keys[off + lane] : ~0ull;
        v = warp_bitonic(v, lane);
        unsigned long long pv = __shfl_up_sync(FULL, v, 1);
        bool head = (lane < (int)L) && (lane == 0 || (unsigned)(pv >> 24) != (unsigned)(v >> 24));
        u = __popc(__ballot_sync(FULL, head));
    } else {
        if (lane == 0) {
            for (unsigned i = 1; i < L; i++) {
                unsigned long long key = g_keys[off + i];
                int j = (int)i - 1;
                while (j >= 0 && g_keys[off + j] > key) {
                    g_keys[off + j + 1] = g_keys[off + j];
                    j--;
                }
                g_keys[off + j + 1] = key;
            }
            unsigned prevb = 0xFFFFFFFFu;
            for (unsigned i = 0; i < L; i++) {
                unsigned b = (unsigned)(g_keys[off + i] >> 24);
                if (b != prevb) { u++; prevb = b; }
            }
        }
        u = __shfl_sync(FULL, u, 0);
    }
    if (lane == 0) g_ucnt[gw] = u;
}

__global__ void k_sort2(int N) {
    int gw = (blockIdx.x * blockDim.x + threadIdx.x) >> 5;
    int lane = threadIdx.x & 31;
    if (gw >= N) return;
    unsigned off = g_boff[gw];
    unsigned L = g_bcnt[gw];
    if (L == 0) return;
    unsigned rb = g_urank[gw];
    if (L <= 32u) {
        unsigned long long v = (lane < (int)L) ? g_keys[off + lane] : ~0ull;
        v = warp_bitonic(v, lane);
        unsigned long long pv = __shfl_up_sync(FULL, v, 1);
        bool head = (lane < (int)L) && (lane == 0 || (unsigned)(pv >> 24) != (unsigned)(v >> 24));
        unsigned bal = __ballot_sync(FULL, head);
        if (lane < (int)L) {
            unsigned rank = rb + __popc(bal & ((2u << lane) - 1u)) - 1u;
            unsigned slot = (unsigned)(v & 0xFFFFFFull);
            g_idxmap[slot] = (int)rank;
            if (head) {
                g_uea[rank] = gw;
                g_ueb[rank] = (int)(unsigned)(v >> 24);
            }
        }
    } else {
        if (lane == 0) {   // keys already sorted by k_sort1 fallback
            unsigned prevb = 0xFFFFFFFFu;
            unsigned u = 0;
            for (unsigned i = 0; i < L; i++) {
                unsigned long long k = g_keys[off + i];
                unsigned b = (unsigned)(k >> 24);
                if (b != prevb) { u++; prevb = b; g_uea[rb + u - 1] = gw; g_ueb[rb + u - 1] = (int)b; }
                g_idxmap[(unsigned)(k & 0xFFFFFFull)] = (int)(rb + u - 1);
            }
        }
    }
}

// ---------------------------------------------------------------------------
// interp: output section 0
// ---------------------------------------------------------------------------
__global__ void k_interp(const float* __restrict__ pos, const float* __restrict__ sdf,
                         const float* __restrict__ thp, float* __restrict__ out) {
    unsigned E = g_cnt[0];
    unsigned base = blockIdx.x * (TPB * 4u) + threadIdx.x;
    if (base >= E) return;
    float th = *thp;
#pragma unroll
    for (int k4 = 0; k4 < 4; k4++) {
        unsigned r = base + k4 * TPB;
        if (r >= E) break;
        int a = g_uea[r], b = g_ueb[r];
        float s0 = sdf[a], s1 = sdf[b];
        if (s0 > 0.0f && s1 > 0.0f) { s0 -= th; s1 -= th; }
        float denom = s0 - s1;
        float w0 = -s1 / denom;
        float w1 = s0 / denom;
#pragma unroll
        for (int k = 0; k < 3; k++)
            out[3 * (size_t)r + k] = pos[3 * a + k] * w0 + pos[3 * b + k] * w1;
    }
}

// ---------------------------------------------------------------------------
// fused emit: local flag re-scan + faces + all_tets build
// ---------------------------------------------------------------------------
__global__ void k_emit(const int4* __restrict__ tet, int F, int N, float* __restrict__ out) {
    __shared__ unsigned long long sh[TPB];
    int t = threadIdx.x, blk = blockIdx.x;
    int base = blk * (TPB * 8) + t * 8;
    unsigned lti[8];
    unsigned long long p = 0;
#pragma unroll
    for (int i = 0; i < 8; i++) {
        int f = base + i;
        lti[i] = (f < F) ? (unsigned)g_ti[f] : 0u;
        p += packflags(lti[i]);
    }
    sh[t] = p; __syncthreads();
    for (int d = 1; d < TPB; d <<= 1) {
        unsigned long long y = 0;
        if (t >= d) y = sh[t - d];
        __syncthreads();
        if (t >= d) sh[t] += y;
        __syncthreads();
    }
    unsigned long long run = (t > 0) ? sh[t - 1] : 0ull;
    unsigned b0 = g_partf[0 * 1024 + blk], b1 = g_partf[1 * 1024 + blk];
    unsigned b2 = g_partf[2 * 1024 + blk], b3 = g_partf[3 * 1024 + blk];
    unsigned b4 = g_partf[4 * 1024 + blk];
    unsigned E = g_cnt[0], NT1 = g_cnt[1], T1 = g_cnt[3], T3 = g_cnt[4];
    float* fo = out + 3 * (size_t)E;
#pragma unroll
    for (int i = 0; i < 8; i++) {
        int f = base + i;
        if (f >= F) break;
        unsigned ti = lti[i];
        if (f_valid(ti)) {
            unsigned trioff = f_nt1(ti)  ? b0 + (unsigned)(run & 0xFFF)
                                         : b1 + (unsigned)((run >> 12) & 0xFFF);
            unsigned tetoff = f_ntt1(ti) ? b2 + (unsigned)((run >> 24) & 0xFFF)
                                         : b3 + (unsigned)((run >> 36) & 0xFFF);
            int4 q = tet[f];
            int v[4] = {q.x, q.y, q.z, q.w};
            // faces
            if (f_nt1(ti)) {
                size_t fb = 3 * (size_t)trioff;
#pragma unroll
                for (int j = 0; j < 3; j++)
                    fo[fb + j] = (float)g_idxmap[6 * f + d_tri[ti][j]];
            } else {
                size_t fb = 3 * (size_t)NT1 + 6 * (size_t)trioff;
#pragma unroll
                for (int j = 0; j < 6; j++)
                    fo[fb + j] = (float)g_idxmap[6 * f + d_tri[ti][j]];
            }
            // tets
            if (f_ntt1(ti)) {
                int r[4];
#pragma unroll
                for (int j = 0; j < 4; j++) {
                    int c = d_tet[ti][j];
                    r[j] = (c < 4) ? v[c] : N + g_idxmap[6 * f + (c - 4)];
                }
                g_alltets[tetoff] = make_int4(r[0], r[1], r[2], r[3]);
            } else {
                unsigned rowbase = T1 + 3u * tetoff;
#pragma unroll
                for (int t3i = 0; t3i < 3; t3i++) {
                    int r[4];
#pragma unroll
                    for (int j = 0; j < 4; j++) {
                        int c = d_tet[ti][4 * t3i + j];
                        r[j] = (c < 4) ? v[c] : N + g_idxmap[6 * f + (c - 4)];
                    }
                    g_alltets[rowbase + t3i] = make_int4(r[0], r[1], r[2], r[3]);
                }
            }
        } else if (ti == 15u) {
            unsigned tetoff = b4 + (unsigned)((run >> 48) & 0xFFF);
            g_alltets[T1 + 3u * T3 + tetoff] = tet[f];
        }
        run += packflags(ti);
    }
}

// ---------------------------------------------------------------------------
// tetmesh unique: presence bytes over [0, N+E)
// ---------------------------------------------------------------------------
__global__ void k_clear_pres() {
    unsigned n = g_cnt[9];
    unsigned nw = (n + 15u) / 16u;
    unsigned i = blockIdx.x * blockDim.x + threadIdx.x;
    if (i >= nw) return;
    g_pres4[i] = make_uint4(0u, 0u, 0u, 0u);
}

__global__ void k_mark() {
    unsigned T = g_cnt[8];
    unsigned base = blockIdx.x * (TPB * 4u) + threadIdx.x;
    if (base >= T) return;
    unsigned char* pres = (unsigned char*)g_pres4;
#pragma unroll
    for (int k4 = 0; k4 < 4; k4++) {
        unsigned i = base + k4 * TPB;
        if (i >= T) break;
        int4 q = g_alltets[i];
        pres[q.x] = 1; pres[q.y] = 1; pres[q.z] = 1; pres[q.w] = 1;
    }
}

__global__ void ps_k1() {
    __shared__ unsigned sh[TPB];
    unsigned n = g_cnt[9];
    int t = threadIdx.x;
    unsigned blockByteBase = blockIdx.x * (TPB * 16u);
    if (blockByteBase >= n) {
        if (t == 0) g_part2[blockIdx.x] = 0u;
        return;
    }
    const unsigned* w = (const unsigned*)g_pres4;
    const unsigned NW = (MAXVAL + 3) / 4;
    unsigned base = blockIdx.x * (TPB * 4u) + t * 4u;
    unsigned s = 0;
#pragma unroll
    for (int i = 0; i < 4; i++) {
        unsigned idx = base + i;
        if (idx < NW) s += (w[idx] * 0x01010101u) >> 24;
    }
    sh[t] = s; __syncthreads();
    for (int d = TPB / 2; d > 0; d >>= 1) {
        if (t < d) sh[t] += sh[t + d];
        __syncthreads();
    }
    if (t == 0) g_part2[blockIdx.x] = sh[0];
}

__global__ void ps_k2(int nb) {
    __shared__ unsigned sh[1024];
    __shared__ unsigned carry_s;
    int t = threadIdx.x;
    if (t == 0) carry_s = 0;
    __syncthreads();
    for (int base = 0; base < nb; base += 1024) {
        int i = base + t;
        unsigned x = (i < nb) ? g_part2[i] : 0u;
        sh[t] = x; __syncthreads();
        for (int d = 1; d < 1024; d <<= 1) {
            unsigned y = 0;
            if (t >= d) y = sh[t - d];
            __syncthreads();
            if (t >= d) sh[t] += y;
            __syncthreads();
        }
        unsigned c = carry_s;
        unsigned excl = c + ((t > 0) ? sh[t - 1] : 0u);
        unsigned tot = sh[1023];
        __syncthreads();
        if (i < nb) g_part2[i] = excl;
        if (t == 0) carry_s = c + tot;
        __syncthreads();
    }
    if (t == 0) g_cnt[6] = carry_s;
}

__global__ void ps_k3() {
    __shared__ unsigned sh[TPB];
    unsigned n = g_cnt[9];
    int t = threadIdx.x;
    unsigned blockByteBase = blockIdx.x * (TPB * 16u);
    if (blockByteBase >= n) return;
    const unsigned* w = (const unsigned*)g_pres4;
    const unsigned NW = (MAXVAL + 3) / 4;
    unsigned base = blockIdx.x * (TPB * 4u) + t * 4u;
    unsigned wv[4]; unsigned s = 0;
#pragma unroll
    for (int i = 0; i < 4; i++) {
        unsigned idx = base + i;
        wv[i] = (idx < NW) ? w[idx] : 0u;
        s += (wv[i] * 0x01010101u) >> 24;
    }
    sh[t] = s; __syncthreads();
    for (int d = 1; d < TPB; d <<= 1) {
        unsigned y = 0;
        if (t >= d) y = sh[t - d];
        __syncthreads();
        if (t >= d) sh[t] += y;
        __syncthreads();
    }
    unsigned run = g_part2[blockIdx.x] + ((t > 0) ? sh[t - 1] : 0u);
#pragma unroll
    for (int i = 0; i < 4; i++) {
        unsigned v = wv[i];
        unsigned byteBase = (base + i) * 4u;
#pragma unroll
        for (int bt = 0; bt < 4; bt++) {
            if ((v >> (8 * bt)) & 1u) {
                g_rank2[byteBase + bt] = run;
                run++;
            }
        }
    }
}

__global__ void k_vt(const float* __restrict__ pos, int N, float* __restrict__ out) {
    unsigned n = g_cnt[9];
    unsigned base = blockIdx.x * (TPB * 4u) + threadIdx.x;
    if (base >= n) return;
    const unsigned char* pres = (const unsigned char*)g_pres4;
    unsigned E = g_cnt[0];
    unsigned Nf = g_cnt[1] + 2u * g_cnt[2];
    size_t ofs = (size_t)3 * E + (size_t)3 * Nf;
#pragma unroll
    for (int k4 = 0; k4 < 4; k4++) {
        unsigned v = base + k4 * TPB;
        if (v >= n) break;
        if (!pres[v]) continue;
        unsigned r = g_rank2[v];
#pragma unroll
        for (int k = 0; k < 3; k++)
            out[ofs + 3 * (size_t)r + k] =
                (v < (unsigned)N) ? pos[3 * v + k] : out[3 * (size_t)(v - N) + k];
    }
}

__global__ void k_tets_out(float* __restrict__ out) {
    unsigned T = g_cnt[8];
    unsigned base = blockIdx.x * (TPB * 4u) + threadIdx.x;
    if (base >= T) return;
    unsigned E = g_cnt[0];
    unsigned Nf = g_cnt[1] + 2u * g_cnt[2];
    unsigned U = g_cnt[6];
    size_t ofs = (size_t)3 * E + (size_t)3 * Nf + (size_t)3 * U;
#pragma unroll
    for (int k4 = 0; k4 < 4; k4++) {
        unsigned i = base + k4 * TPB;
        if (i >= T) break;
        int4 q = g_alltets[i];
        out[ofs + 4 * (size_t)i + 0] = (float)g_rank2[q.x];
        out[ofs + 4 * (size_t)i + 1] = (float)g_rank2[q.y];
        out[ofs + 4 * (size_t)i + 2] = (float)g_rank2[q.z];
        out[ofs + 4 * (size_t)i + 3] = (float)g_rank2[q.w];
    }
}

// ---------------------------------------------------------------------------
// kernel_launch
// ---------------------------------------------------------------------------
extern "C" void kernel_launch(void* const* d_in, const int* in_sizes, int n_in,
                              void* d_out, int out_size) {
    const float* pos = (const float*)d_in[0];
    const float* sdf = (const float*)d_in[1];
    const int4*  tet = (const int4*)d_in[2];
    const float* th  = (const float*)d_in[3];
    float* out = (float*)d_out;

    int N = in_sizes[1];
    int F = in_sizes[2] / 4;

    int warpsN = (N + 127) / 128;
    k_init<<<GRID(warpsN * 32), TPB>>>(sdf, th, N);
    k_ti<<<GRID(F), TPB>>>(tet, F);

    int nbf = (F + TPB * 8 - 1) / (TPB * 8);
    fs_k1<<<nbf, TPB>>>(F);
    fs_k2<<<1, 1024>>>(nbf);

    run_scan(0, 1, N, -1, N);              // bcnt -> boff
    k_scatter<<<GRID(F), TPB>>>(tet, F);
    k_sort1<<<GRID(N * 32), TPB>>>(N);
    run_scan(2, 3, N, 0, N);               // ucnt -> urank; sets E, T, N+E
    k_sort2<<<GRID(N * 32), TPB>>>(N);

    k_interp<<<GRID(MAXE / 4), TPB>>>(pos, sdf, th, out);
    k_emit<<<nbf, TPB>>>(tet, F, N, out);

    k_clear_pres<<<GRID(MAXVAL / 16 + 1), TPB>>>();
    k_mark<<<GRID(MAXT / 4), TPB>>>();
    int nbp = ((MAXVAL + 3) / 4 + TPB * 4 - 1) / (TPB * 4);
    ps_k1<<<nbp, TPB>>>();
    ps_k2<<<1, 1024>>>(nbp);
    ps_k3<<<nbp, TPB>>>();

    k_vt<<<GRID(MAXVAL / 4 + 1), TPB>>>(pos, N, out);
    k_tets_out<<<GRID(MAXT / 4), TPB>>>(out);
}

// round 5
// speedup vs baseline: 1.1819x; 1.1819x over previous
#include <cuda_runtime.h>

#define MAXN 400000
#define MAXF 2000000
#define MAXE (4 * MAXF)             // max crossing edges (<=4 per valid tet)
#define MAXSLOTNS (6 * MAXF)        // slot namespace (6f+e) for idxmap
#define MAXVAL (MAXN + MAXE)
#define MAXT (3 * MAXF)
#define TPB 256
#define GRID(n) (((n) + TPB - 1) / TPB)
#define FULL 0xffffffffu

// ---------------------------------------------------------------------------
// Tables
// ---------------------------------------------------------------------------
__device__ const int d_tri[16][6] = {
    {-1,-1,-1,-1,-1,-1},{1,0,2,-1,-1,-1},{4,0,3,-1,-1,-1},{1,4,2,1,3,4},
    {3,1,5,-1,-1,-1},{2,3,0,2,5,3},{1,4,0,1,5,4},{4,2,5,-1,-1,-1},
    {4,5,2,-1,-1,-1},{4,1,0,4,5,1},{3,2,0,3,5,2},{1,3,5,-1,-1,-1},
    {4,1,2,4,3,1},{3,0,4,-1,-1,-1},{2,0,1,-1,-1,-1},{-1,-1,-1,-1,-1,-1}};
__device__ const int d_tet[16][12] = {
    {-1,-1,-1,-1,-1,-1,-1,-1,-1,-1,-1,-1},{0,4,5,6,-1,-1,-1,-1,-1,-1,-1,-1},
    {1,4,8,7,-1,-1,-1,-1,-1,-1,-1,-1},{7,1,8,6,5,1,7,6,5,0,1,6},
    {2,5,7,9,-1,-1,-1,-1,-1,-1,-1,-1},{4,0,6,7,9,0,7,6,7,0,9,2},
    {4,1,9,8,5,1,9,4,5,1,2,9},{6,0,1,2,8,6,1,2,9,6,8,2},
    {3,6,9,8,-1,-1,-1,-1,-1,-1,-1,-1},{5,0,4,8,5,0,8,3,5,8,9,3},
    {1,4,7,3,4,7,6,3,9,6,7,3},{0,1,5,3,5,1,9,3,5,1,7,9},
    {5,2,3,7,3,6,5,8,3,5,7,8},{0,4,7,8,0,3,8,7,0,3,7,2},
    {4,1,2,3,4,3,2,5,4,3,5,6},{0,1,2,3,-1,-1,-1,-1,-1,-1,-1,-1}};
__device__ const int d_be[12] = {0,1, 0,2, 0,3, 1,2, 1,3, 2,3};

__device__ __forceinline__ unsigned f_valid(unsigned ti) { return (0x7FFEu >> ti) & 1u; }
__device__ __forceinline__ unsigned f_nt1(unsigned ti)   { return (0x6996u >> ti) & 1u; }
__device__ __forceinline__ unsigned f_ntt1(unsigned ti)  { return (0x0116u >> ti) & 1u; }

__device__ __forceinline__ unsigned long long packflags(unsigned ti) {
    unsigned v  = f_valid(ti);
    unsigned n1 = v & f_nt1(ti);
    unsigned t1 = v & f_ntt1(ti);
    unsigned n2 = v ^ n1;
    unsigned t3 = v ^ t1;
    unsigned in = (ti == 15u) ? 1u : 0u;
    return (unsigned long long)n1
         | ((unsigned long long)n2 << 12)
         | ((unsigned long long)t1 << 24)
         | ((unsigned long long)t3 << 36)
         | ((unsigned long long)in << 48);
}

__device__ __forceinline__ unsigned warp_iscan_u32(unsigned x, int lane) {
#pragma unroll
    for (int d = 1; d < 32; d <<= 1) {
        unsigned y = __shfl_up_sync(FULL, x, d);
        if (lane >= d) x += y;
    }
    return x;
}

__device__ __forceinline__ unsigned long long warp_iscan_u64(unsigned long long x, int lane) {
#pragma unroll
    for (int d = 1; d < 32; d <<= 1) {
        unsigned long long y = __shfl_up_sync(FULL, x, d);
        if (lane >= d) x += y;
    }
    return x;
}

// ---------------------------------------------------------------------------
// Scratch
// ---------------------------------------------------------------------------
__device__ unsigned           g_obits[(MAXN + 31) / 32];
__device__ unsigned char      g_ti[MAXF];
__device__ unsigned           g_bcnt[MAXN];
__device__ unsigned           g_boff[MAXN];
__device__ unsigned           g_bfill[MAXN];
__device__ unsigned           g_ucnt[MAXN];
__device__ unsigned           g_urank[MAXN];
__device__ unsigned long long g_keys[MAXE];
__device__ unsigned           g_aux[MAXE];
__device__ int                g_idxmap[MAXSLOTNS];
__device__ int                g_uea[MAXE];
__device__ int                g_ueb[MAXE];
__device__ int4               g_alltets[MAXT];
__device__ uint4              g_pres4[(MAXVAL + 15) / 16];
__device__ unsigned           g_rank2[MAXVAL];
__device__ unsigned           g_partf[5 * 1024];
__device__ unsigned           g_part2[4096];
__device__ unsigned           g_cnt[16];
// g_cnt: [0]=E [1]=NT1 [2]=NT2 [3]=T1 [4]=T3 [5]=INNER [6]=U [8]=T [9]=N+E

// ---------------------------------------------------------------------------
// init: occ bitset via ballot + clear bucket counters
// ---------------------------------------------------------------------------
__global__ void k_init(const float* __restrict__ sdf, const float* __restrict__ th, int N) {
    int gt = blockIdx.x * blockDim.x + threadIdx.x;
    int lane = threadIdx.x & 31;
    int warp = gt >> 5;
    float t = *th;
    int base = warp * 128;
#pragma unroll
    for (int it = 0; it < 4; it++) {
        int v = base + it * 32 + lane;
        unsigned o = 0;
        if (v < N) { float s = sdf[v]; o = (s > 0.0f && s <= t) ? 1u : 0u; }
        unsigned bal = __ballot_sync(FULL, o);
        if (lane == 0 && base + it * 32 < N) g_obits[warp * 4 + it] = bal;
    }
    int i4 = gt * 4;
#pragma unroll
    for (int j = 0; j < 4; j++) {
        int i = i4 + j;
        if (i < N) { g_bcnt[i] = 0u; g_bfill[i] = 0u; }
    }
}

// ---------------------------------------------------------------------------
// classify + bucket histogram + fused 5-channel flag block-reduce
// grid = nbf = ceil(F / 2048); strided element access (coalesced)
// ---------------------------------------------------------------------------
__global__ void k_ti(const int4* __restrict__ tet, int F) {
    __shared__ unsigned long long sh64[8];
    int t = threadIdx.x, lane = t & 31, wid = t >> 5;
    int blk = blockIdx.x;
    unsigned long long p = 0;
#pragma unroll
    for (int i = 0; i < 8; i++) {
        int f = blk * 2048 + i * TPB + t;
        if (f >= F) break;
        int4 q = tet[f];
        int v[4] = {q.x, q.y, q.z, q.w};
        unsigned ti = ((g_obits[v[0] >> 5] >> (v[0] & 31)) & 1u)
                    | (((g_obits[v[1] >> 5] >> (v[1] & 31)) & 1u) << 1)
                    | (((g_obits[v[2] >> 5] >> (v[2] & 31)) & 1u) << 2)
                    | (((g_obits[v[3] >> 5] >> (v[3] & 31)) & 1u) << 3);
        g_ti[f] = (unsigned char)ti;
        p += packflags(ti);
        if (f_valid(ti)) {
#pragma unroll
            for (int e = 0; e < 6; e++) {
                int p0 = d_be[2 * e], p1 = d_be[2 * e + 1];
                if (((ti >> p0) ^ (ti >> p1)) & 1u) {
                    int a = v[p0], b = v[p1];
                    int amin = a < b ? a : b;
                    atomicAdd(&g_bcnt[amin], 1u);
                }
            }
        }
    }
#pragma unroll
    for (int d = 16; d > 0; d >>= 1)
        p += __shfl_xor_sync(FULL, p, d);
    if (lane == 0) sh64[wid] = p;
    __syncthreads();
    if (t == 0) {
        unsigned long long s = 0;
#pragma unroll
        for (int i = 0; i < 8; i++) s += sh64[i];
        g_partf[0 * 1024 + blk] = (unsigned)(s & 0xFFF);
        g_partf[1 * 1024 + blk] = (unsigned)((s >> 12) & 0xFFF);
        g_partf[2 * 1024 + blk] = (unsigned)((s >> 24) & 0xFFF);
        g_partf[3 * 1024 + blk] = (unsigned)((s >> 36) & 0xFFF);
        g_partf[4 * 1024 + blk] = (unsigned)((s >> 48) & 0xFFF);
    }
}

// 5-channel partial scan (single block of 1024, shfl hierarchical)
__global__ void fs_k2(int nb) {
    __shared__ unsigned shw[32];
    int t = threadIdx.x, lane = t & 31, wid = t >> 5;
    for (int c = 0; c < 5; c++) {
        unsigned* arr = g_partf + c * 1024;
        int base = t * 4;
        unsigned v[4]; unsigned s = 0;
#pragma unroll
        for (int i = 0; i < 4; i++) {
            unsigned x = (base + i < nb) ? arr[base + i] : 0u;
            v[i] = s; s += x;
        }
        unsigned inc = warp_iscan_u32(s, lane);
        if (lane == 31) shw[wid] = inc;
        __syncthreads();
        if (wid == 0) shw[lane] = warp_iscan_u32(shw[lane], lane);   // full warp active
        __syncthreads();
        unsigned wb = (wid > 0) ? shw[wid - 1] : 0u;
        unsigned excl = wb + inc - s;
#pragma unroll
        for (int i = 0; i < 4; i++)
            if (base + i < nb) arr[base + i] = excl + v[i];
        if (t == 0) g_cnt[1 + c] = shw[31];
        __syncthreads();
    }
}

// ---------------------------------------------------------------------------
// Generic u32 scan (bcnt->boff, ucnt->urank)
// ---------------------------------------------------------------------------
__device__ __forceinline__ unsigned* selarr(int s) {
    switch (s) {
        case 0: return g_bcnt;
        case 1: return g_boff;
        case 2: return g_ucnt;
        default: return g_urank;
    }
}

__global__ void s_k1(int insel, int outsel, int n) {
    __shared__ unsigned sh[8];
    const unsigned* in = selarr(insel);
    unsigned* out = selarr(outsel);
    int t = threadIdx.x;
    int base = blockIdx.x * (TPB * 8) + t * 8;
    unsigned v[8]; unsigned s = 0;
#pragma unroll
    for (int i = 0; i < 8; i++) {
        unsigned x = (base + i < n) ? in[base + i] : 0u;
        v[i] = s; s += x;
    }
    int lane = t & 31, wid = t >> 5;
    unsigned inc = warp_iscan_u32(s, lane);
    if (lane == 31) sh[wid] = inc;
    __syncthreads();
    if (wid == 0) {                                   // FIX: whole warp in the shuffle
        unsigned x = (lane < 8) ? sh[lane] : 0u;
        x = warp_iscan_u32(x, lane);
        if (lane < 8) sh[lane] = x;
    }
    __syncthreads();
    unsigned off = ((wid > 0) ? sh[wid - 1] : 0u) + inc - s;
    if (t == TPB - 1) g_part2[blockIdx.x] = off + s;
#pragma unroll
    for (int i = 0; i < 8; i++)
        if (base + i < n) out[base + i] = v[i] + off;
}

__global__ void s_k2(int nb, int counterIdx, int N) {
    __shared__ unsigned shw[32];
    int t = threadIdx.x, lane = t & 31, wid = t >> 5;
    int base = t * 4;
    unsigned v[4]; unsigned s = 0;
#pragma unroll
    for (int i = 0; i < 4; i++) {
        unsigned x = (base + i < nb) ? g_part2[base + i] : 0u;
        v[i] = s; s += x;
    }
    unsigned inc = warp_iscan_u32(s, lane);
    if (lane == 31) shw[wid] = inc;
    __syncthreads();
    if (wid == 0) shw[lane] = warp_iscan_u32(shw[lane], lane);   // 1024 threads: 32 warps, full
    __syncthreads();
    unsigned wb = (wid > 0) ? shw[wid - 1] : 0u;
    unsigned excl = wb + inc - s;
#pragma unroll
    for (int i = 0; i < 4; i++)
        if (base + i < nb) g_part2[base + i] = excl + v[i];
    if (t == 0 && counterIdx >= 0) {
        unsigned total = shw[31];
        g_cnt[counterIdx] = total;
        if (counterIdx == 0) {
            g_cnt[8] = g_cnt[3] + 3u * g_cnt[4] + g_cnt[5];
            g_cnt[9] = (unsigned)N + total;
        }
    }
}

__global__ void s_k3(int outsel, int n) {
    unsigned* out = selarr(outsel);
    unsigned add = g_part2[blockIdx.x];
    int base = blockIdx.x * (TPB * 8) + threadIdx.x * 8;
#pragma unroll
    for (int i = 0; i < 8; i++)
        if (base + i < n) out[base + i] += add;
}

static void run_scan(int insel, int outsel, int n, int counterIdx, int N) {
    int nb = (n + TPB * 8 - 1) / (TPB * 8);
    s_k1<<<nb, TPB>>>(insel, outsel, n);
    s_k2<<<1, 1024>>>(nb, counterIdx, N);
    s_k3<<<nb, TPB>>>(outsel, n);
}

// ---------------------------------------------------------------------------
// scatter crossing edges into buckets
// ---------------------------------------------------------------------------
__global__ void k_scatter(const int4* __restrict__ tet, int F) {
    int f = blockIdx.x * blockDim.x + threadIdx.x;
    if (f >= F) return;
    unsigned ti = g_ti[f];
    if (!f_valid(ti)) return;
    int4 q = tet[f];
    int v[4] = {q.x, q.y, q.z, q.w};
#pragma unroll
    for (int e = 0; e < 6; e++) {
        int p0 = d_be[2 * e], p1 = d_be[2 * e + 1];
        if (((ti >> p0) ^ (ti >> p1)) & 1u) {
            int a = v[p0], b = v[p1];
            int amin = a < b ? a : b;
            int bmax = a < b ? b : a;
            unsigned p = g_boff[amin] + atomicAdd(&g_bfill[amin], 1u);
            unsigned slot = (unsigned)(6 * f + e);
            g_keys[p] = ((unsigned long long)(unsigned)bmax << 24) | (unsigned long long)slot;
        }
    }
}

// ---------------------------------------------------------------------------
// thread-per-bucket insertion sort + local unique ranks (R2 version)
// ---------------------------------------------------------------------------
__global__ void k_sort(int N) {
    int a = blockIdx.x * blockDim.x + threadIdx.x;
    if (a >= N) return;
    unsigned off = g_boff[a];
    unsigned L = g_bcnt[a];
    for (unsigned i = 1; i < L; i++) {
        unsigned long long key = g_keys[off + i];
        int j = (int)i - 1;
        while (j >= 0 && g_keys[off + j] > key) {
            g_keys[off + j + 1] = g_keys[off + j];
            j--;
        }
        g_keys[off + j + 1] = key;
    }
    unsigned u = 0;
    unsigned prevb = 0xFFFFFFFFu;
    for (unsigned i = 0; i < L; i++) {
        unsigned long long k = g_keys[off + i];
        unsigned b = (unsigned)(k >> 24);
        unsigned head = (b != prevb) ? 1u : 0u;
        if (head) { u++; prevb = b; }
        g_aux[off + i] = ((u - 1) << 1) | head;
    }
    g_ucnt[a] = u;
}

__global__ void k_efinal(int N) {
    int a = blockIdx.x * blockDim.x + threadIdx.x;
    if (a >= N) return;
    unsigned off = g_boff[a];
    unsigned L = g_bcnt[a];
    unsigned rb = g_urank[a];
    for (unsigned i = 0; i < L; i++) {
        unsigned long long k = g_keys[off + i];
        unsigned aux = g_aux[off + i];
        unsigned rank = rb + (aux >> 1);
        unsigned slot = (unsigned)(k & 0xFFFFFFull);
        g_idxmap[slot] = (int)rank;
        if (aux & 1u) {
            g_uea[rank] = a;
            g_ueb[rank] = (int)(unsigned)(k >> 24);
        }
    }
}

// ---------------------------------------------------------------------------
// interp: output section 0
// ---------------------------------------------------------------------------
__global__ void k_interp(const float* __restrict__ pos, const float* __restrict__ sdf,
                         const float* __restrict__ thp, float* __restrict__ out) {
    unsigned E = g_cnt[0];
    unsigned base = blockIdx.x * (TPB * 4u) + threadIdx.x;
    if (base >= E) return;
    float th = *thp;
#pragma unroll
    for (int k4 = 0; k4 < 4; k4++) {
        unsigned r = base + k4 * TPB;
        if (r >= E) break;
        int a = g_uea[r], b = g_ueb[r];
        float s0 = sdf[a], s1 = sdf[b];
        if (s0 > 0.0f && s1 > 0.0f) { s0 -= th; s1 -= th; }
        float denom = s0 - s1;
        float w0 = -s1 / denom;
        float w1 = s0 / denom;
#pragma unroll
        for (int k = 0; k < 3; k++)
            out[3 * (size_t)r + k] = pos[3 * a + k] * w0 + pos[3 * b + k] * w1;
    }
}

// ---------------------------------------------------------------------------
// fused emit: local flag re-scan (shfl) + faces + all_tets build
// ---------------------------------------------------------------------------
__global__ void k_emit(const int4* __restrict__ tet, int F, int N, float* __restrict__ out) {
    __shared__ unsigned long long sh64[8];
    int t = threadIdx.x, lane = t & 31, wid = t >> 5;
    int blk = blockIdx.x;
    int base = blk * (TPB * 8) + t * 8;
    unsigned lti[8];
    unsigned long long p = 0;
#pragma unroll
    for (int i = 0; i < 8; i++) {
        int f = base + i;
        lti[i] = (f < F) ? (unsigned)g_ti[f] : 0u;
        p += packflags(lti[i]);
    }
    unsigned long long inc = warp_iscan_u64(p, lane);
    if (lane == 31) sh64[wid] = inc;
    __syncthreads();
    if (t == 0) {
        unsigned long long runw = 0;
#pragma unroll
        for (int i = 0; i < 8; i++) { unsigned long long x = sh64[i]; sh64[i] = runw; runw += x; }
    }
    __syncthreads();
    unsigned long long run = sh64[wid] + inc - p;
    unsigned b0 = g_partf[0 * 1024 + blk], b1 = g_partf[1 * 1024 + blk];
    unsigned b2 = g_partf[2 * 1024 + blk], b3 = g_partf[3 * 1024 + blk];
    unsigned b4 = g_partf[4 * 1024 + blk];
    unsigned E = g_cnt[0], NT1 = g_cnt[1], T1 = g_cnt[3], T3 = g_cnt[4];
    float* fo = out + 3 * (size_t)E;
#pragma unroll
    for (int i = 0; i < 8; i++) {
        int f = base + i;
        if (f >= F) break;
        unsigned ti = lti[i];
        if (f_valid(ti)) {
            unsigned trioff = f_nt1(ti)  ? b0 + (unsigned)(run & 0xFFF)
                                         : b1 + (unsigned)((run >> 12) & 0xFFF);
            unsigned tetoff = f_ntt1(ti) ? b2 + (unsigned)((run >> 24) & 0xFFF)
                                         : b3 + (unsigned)((run >> 36) & 0xFFF);
            int4 q = tet[f];
            int v[4] = {q.x, q.y, q.z, q.w};
            if (f_nt1(ti)) {
                size_t fb = 3 * (size_t)trioff;
#pragma unroll
                for (int j = 0; j < 3; j++)
                    fo[fb + j] = (float)g_idxmap[6 * f + d_tri[ti][j]];
            } else {
                size_t fb = 3 * (size_t)NT1 + 6 * (size_t)trioff;
#pragma unroll
                for (int j = 0; j < 6; j++)
                    fo[fb + j] = (float)g_idxmap[6 * f + d_tri[ti][j]];
            }
            if (f_ntt1(ti)) {
                int r[4];
#pragma unroll
                for (int j = 0; j < 4; j++) {
                    int c = d_tet[ti][j];
                    r[j] = (c < 4) ? v[c] : N + g_idxmap[6 * f + (c - 4)];
                }
                g_alltets[tetoff] = make_int4(r[0], r[1], r[2], r[3]);
            } else {
                unsigned rowbase = T1 + 3u * tetoff;
#pragma unroll
                for (int t3i = 0; t3i < 3; t3i++) {
                    int r[4];
#pragma unroll
                    for (int j = 0; j < 4; j++) {
                        int c = d_tet[ti][4 * t3i + j];
                        r[j] = (c < 4) ? v[c] : N + g_idxmap[6 * f + (c - 4)];
                    }
                    g_alltets[rowbase + t3i] = make_int4(r[0], r[1], r[2], r[3]);
                }
            }
        } else if (ti == 15u) {
            unsigned tetoff = b4 + (unsigned)((run >> 48) & 0xFFF);
            g_alltets[T1 + 3u * T3 + tetoff] = tet[f];
        }
        run += packflags(ti);
    }
}

// ---------------------------------------------------------------------------
// tetmesh unique: presence bytes over [0, N+E)
// ---------------------------------------------------------------------------
__global__ void k_clear_pres() {
    unsigned n = g_cnt[9];
    unsigned nw = (n + 15u) / 16u;
    unsigned i = blockIdx.x * blockDim.x + threadIdx.x;
    if (i >= nw) return;
    g_pres4[i] = make_uint4(0u, 0u, 0u, 0u);
}

__global__ void k_mark() {
    unsigned T = g_cnt[8];
    unsigned base = blockIdx.x * (TPB * 4u) + threadIdx.x;
    if (base >= T) return;
    unsigned char* pres = (unsigned char*)g_pres4;
#pragma unroll
    for (int k4 = 0; k4 < 4; k4++) {
        unsigned i = base + k4 * TPB;
        if (i >= T) break;
        int4 q = g_alltets[i];
        pres[q.x] = 1; pres[q.y] = 1; pres[q.z] = 1; pres[q.w] = 1;
    }
}

__global__ void ps_k1() {
    __shared__ unsigned sh[8];
    unsigned n = g_cnt[9];
    int t = threadIdx.x, lane = t & 31, wid = t >> 5;
    unsigned blockByteBase = blockIdx.x * (TPB * 16u);
    if (blockByteBase >= n) {
        if (t == 0) g_part2[blockIdx.x] = 0u;
        return;
    }
    const unsigned* w = (const unsigned*)g_pres4;
    const unsigned NW = (MAXVAL + 3) / 4;
    unsigned base = blockIdx.x * (TPB * 4u) + t * 4u;
    unsigned s = 0;
#pragma unroll
    for (int i = 0; i < 4; i++) {
        unsigned idx = base + i;
        if (idx < NW) s += (w[idx] * 0x01010101u) >> 24;
    }
#pragma unroll
    for (int d = 16; d > 0; d >>= 1) s += __shfl_xor_sync(FULL, s, d);
    if (lane == 0) sh[wid] = s;
    __syncthreads();
    if (t == 0) {
        unsigned tot = 0;
#pragma unroll
        for (int i = 0; i < 8; i++) tot += sh[i];
        g_part2[blockIdx.x] = tot;
    }
}

__global__ void ps_k2(int nb) {
    __shared__ unsigned shw[32];
    int t = threadIdx.x, lane = t & 31, wid = t >> 5;
    int base = t * 4;
    unsigned v[4]; unsigned s = 0;
#pragma unroll
    for (int i = 0; i < 4; i++) {
        unsigned x = (base + i < nb) ? g_part2[base + i] : 0u;
        v[i] = s; s += x;
    }
    unsigned inc = warp_iscan_u32(s, lane);
    if (lane == 31) shw[wid] = inc;
    __syncthreads();
    if (wid == 0) shw[lane] = warp_iscan_u32(shw[lane], lane);
    __syncthreads();
    unsigned wb = (wid > 0) ? shw[wid - 1] : 0u;
    unsigned excl = wb + inc - s;
#pragma unroll
    for (int i = 0; i < 4; i++)
        if (base + i < nb) g_part2[base + i] = excl + v[i];
    if (t == 0) g_cnt[6] = shw[31];
}

__global__ void ps_k3() {
    __shared__ unsigned sh[8];
    unsigned n = g_cnt[9];
    int t = threadIdx.x, lane = t & 31, wid = t >> 5;
    unsigned blockByteBase = blockIdx.x * (TPB * 16u);
    if (blockByteBase >= n) return;
    const unsigned* w = (const unsigned*)g_pres4;
    const unsigned NW = (MAXVAL + 3) / 4;
    unsigned base = blockIdx.x * (TPB * 4u) + t * 4u;
    unsigned wv[4]; unsigned s = 0;
#pragma unroll
    for (int i = 0; i < 4; i++) {
        unsigned idx = base + i;
        wv[i] = (idx < NW) ? w[idx] : 0u;
        s += (wv[i] * 0x01010101u) >> 24;
    }
    unsigned inc = warp_iscan_u32(s, lane);
    if (lane == 31) sh[wid] = inc;
    __syncthreads();
    if (t == 0) {
        unsigned runw = 0;
#pragma unroll
        for (int i = 0; i < 8; i++) { unsigned x = sh[i]; sh[i] = runw; runw += x; }
    }
    __syncthreads();
    unsigned run = g_part2[blockIdx.x] + sh[wid] + inc - s;
#pragma unroll
    for (int i = 0; i < 4; i++) {
        unsigned v = wv[i];
        unsigned byteBase = (base + i) * 4u;
#pragma unroll
        for (int bt = 0; bt < 4; bt++) {
            if ((v >> (8 * bt)) & 1u) {
                g_rank2[byteBase + bt] = run;
                run++;
            }
        }
    }
}

__global__ void k_vt(const float* __restrict__ pos, int N, float* __restrict__ out) {
    unsigned n = g_cnt[9];
    unsigned base = blockIdx.x * (TPB * 4u) + threadIdx.x;
    if (base >= n) return;
    const unsigned char* pres = (const unsigned char*)g_pres4;
    unsigned E = g_cnt[0];
    unsigned Nf = g_cnt[1] + 2u * g_cnt[2];
    size_t ofs = (size_t)3 * E + (size_t)3 * Nf;
#pragma unroll
    for (int k4 = 0; k4 < 4; k4++) {
        unsigned v = base + k4 * TPB;
        if (v >= n) break;
        if (!pres[v]) continue;
        unsigned r = g_rank2[v];
#pragma unroll
        for (int k = 0; k < 3; k++)
            out[ofs + 3 * (size_t)r + k] =
                (v < (unsigned)N) ? pos[3 * v + k] : out[3 * (size_t)(v - N) + k];
    }
}

__global__ void k_tets_out(float* __restrict__ out) {
    unsigned T = g_cnt[8];
    unsigned base = blockIdx.x * (TPB * 4u) + threadIdx.x;
    if (base >= T) return;
    unsigned E = g_cnt[0];
    unsigned Nf = g_cnt[1] + 2u * g_cnt[2];
    unsigned U = g_cnt[6];
    size_t ofs = (size_t)3 * E + (size_t)3 * Nf + (size_t)3 * U;
#pragma unroll
    for (int k4 = 0; k4 < 4; k4++) {
        unsigned i = base + k4 * TPB;
        if (i >= T) break;
        int4 q = g_alltets[i];
        out[ofs + 4 * (size_t)i + 0] = (float)g_rank2[q.x];
        out[ofs + 4 * (size_t)i + 1] = (float)g_rank2[q.y];
        out[ofs + 4 * (size_t)i + 2] = (float)g_rank2[q.z];
        out[ofs + 4 * (size_t)i + 3] = (float)g_rank2[q.w];
    }
}

// ---------------------------------------------------------------------------
// kernel_launch
// ---------------------------------------------------------------------------
extern "C" void kernel_launch(void* const* d_in, const int* in_sizes, int n_in,
                              void* d_out, int out_size) {
    const float* pos = (const float*)d_in[0];
    const float* sdf = (const float*)d_in[1];
    const int4*  tet = (const int4*)d_in[2];
    const float* th  = (const float*)d_in[3];
    float* out = (float*)d_out;

    int N = in_sizes[1];
    int F = in_sizes[2] / 4;

    int warpsN = (N + 127) / 128;
    k_init<<<GRID(warpsN * 32), TPB>>>(sdf, th, N);

    int nbf = (F + TPB * 8 - 1) / (TPB * 8);
    k_ti<<<nbf, TPB>>>(tet, F);          // classify + histogram + flag partials
    fs_k2<<<1, 1024>>>(nbf);

    run_scan(0, 1, N, -1, N);            // bcnt -> boff
    k_scatter<<<GRID(F), TPB>>>(tet, F);
    k_sort<<<GRID(N), TPB>>>(N);
    run_scan(2, 3, N, 0, N);             // ucnt -> urank; sets E, T, N+E
    k_efinal<<<GRID(N), TPB>>>(N);

    k_interp<<<GRID(MAXE / 4), TPB>>>(pos, sdf, th, out);
    k_emit<<<nbf, TPB>>>(tet, F, N, out);

    k_clear_pres<<<GRID(MAXVAL / 16 + 1), TPB>>>();
    k_mark<<<GRID(MAXT / 4), TPB>>>();
    int nbp = ((MAXVAL + 3) / 4 + TPB * 4 - 1) / (TPB * 4);
    ps_k1<<<nbp, TPB>>>();
    ps_k2<<<1, 1024>>>(nbp);
    ps_k3<<<nbp, TPB>>>();

    k_vt<<<GRID(MAXVAL / 4 + 1), TPB>>>(pos, N, out);
    k_tets_out<<<GRID(MAXT / 4), TPB>>>(out);
}